// round 15
// baseline (speedup 1.0000x reference)
#include <cuda_runtime.h>
#include <cuda_fp16.h>
#include <cstdint>

#define TT 256
#define NLSTM 128
#define ACHP 18432                 // padded A chunk: 128 rows x 144B
#define SLOTP (16*ACHP)            // per A slot per matrix
#define BCHP 4608                  // padded W chunk: 32 rows x 144B
#define WCTAP (16*BCHP)            // 73728 per CTA per matrix
#define FCDP (16*ACHP)             // FC W d-tile per matrix
#define RSCALE 2048.0f             // residual scale 2^11 (exact)
#define RINV (1.0f/2048.0f)

// ------------------------- device scratch -------------------------
__device__ __align__(128) unsigned char g_Ahi[(size_t)(TT+1)*SLOTP];
__device__ __align__(128) unsigned char g_Alo[(size_t)(TT+1)*SLOTP];   // scaled resid (FC only)
__device__ __align__(128) unsigned char g_WsHi[(size_t)NLSTM*WCTAP];
__device__ __align__(128) unsigned char g_WsLo[(size_t)NLSTM*WCTAP];   // scaled resid
__device__ __align__(128) unsigned char g_W0Hi[(size_t)NLSTM*WCTAP];
__device__ __align__(128) unsigned char g_W0Lo[(size_t)NLSTM*WCTAP];
__device__ __align__(128) unsigned char g_FcHi[(size_t)8*FCDP];
__device__ __align__(128) unsigned char g_FcLo[(size_t)8*FCDP];
__device__ float g_biasP[NLSTM*32];
__device__ unsigned g_bar;
__device__ unsigned g_fcitem;

// ------------------------- helpers -------------------------
__device__ __forceinline__ uint32_t smem_u32(const void* p) {
    uint32_t a;
    asm("{ .reg .u64 t; cvta.to.shared.u64 t, %1; cvt.u32.u64 %0, t; }" : "=r"(a) : "l"(p));
    return a;
}
__device__ __forceinline__ void cpa16(uint32_t dst, const void* src) {
    asm volatile("cp.async.cg.shared.global [%0], [%1], 16;" :: "r"(dst), "l"(src));
}
#define CP_COMMIT() asm volatile("cp.async.commit_group;")
#define CP_WAIT1()  asm volatile("cp.async.wait_group 1;")
#define CP_WAIT0()  asm volatile("cp.async.wait_group 0;")

__device__ __forceinline__ void hmma(float* c, const uint32_t* a, uint32_t b0, uint32_t b1) {
    asm volatile(
        "mma.sync.aligned.m16n8k16.row.col.f32.f16.f16.f32 "
        "{%0,%1,%2,%3}, {%4,%5,%6,%7}, {%8,%9}, {%0,%1,%2,%3};"
        : "+f"(c[0]), "+f"(c[1]), "+f"(c[2]), "+f"(c[3])
        : "r"(a[0]), "r"(a[1]), "r"(a[2]), "r"(a[3]), "r"(b0), "r"(b1));
}
__device__ __forceinline__ float sigf(float x)  { return 1.0f / (1.0f + __expf(-x)); }
__device__ __forceinline__ float tanhx(float x) { return 2.0f / (1.0f + __expf(-2.0f * x)) - 1.0f; }

// fp16 split: hi = fp16(v), lo = fp16((v - hi) * 2^11)   (lo kept normal-range)
__device__ __forceinline__ void pack8h(const float* v, uint4& hi, uint4& lo) {
    uint32_t* hw = (uint32_t*)&hi; uint32_t* lw = (uint32_t*)&lo;
#pragma unroll
    for (int q = 0; q < 4; q++) {
        __half h0 = __float2half(v[2*q]), h1 = __float2half(v[2*q+1]);
        __half l0 = __float2half((v[2*q]   - __half2float(h0)) * RSCALE);
        __half l1 = __float2half((v[2*q+1] - __half2float(h1)) * RSCALE);
        __half2 ph = __halves2half2(h0, h1), pl = __halves2half2(l0, l1);
        hw[q] = *(uint32_t*)&ph; lw[q] = *(uint32_t*)&pl;
    }
}

// ------------------------- prep -------------------------
__global__ void prep(const float* __restrict__ hT, const float* __restrict__ Wih,
                     const float* __restrict__ Whh, const float* __restrict__ bih,
                     const float* __restrict__ bhh, const float* __restrict__ Wfc)
{
    size_t idx = (size_t)blockIdx.x * blockDim.x + threadIdx.x;
    size_t str = (size_t)gridDim.x * blockDim.x;
    if (idx == 0) { g_bar = 0; g_fcitem = 0; }

    for (size_t i = idx; i < (size_t)524288; i += str) {
        int kg = (int)(i & 127), np = (int)((i >> 7) & 31), cta = (int)(i >> 12);
        int row = (np & 3) * 1024 + cta * 8 + (np >> 2);
        int k = kg * 8;
        float wi[8], ws[8];
#pragma unroll
        for (int e = 0; e < 8; e++) {
            float a = Wih[(size_t)row * 1024 + k + e];
            wi[e] = a; ws[e] = a + Whh[(size_t)row * 1024 + k + e];
        }
        size_t base = (size_t)cta * WCTAP + (size_t)(kg >> 3) * BCHP + np * 144 + (kg & 7) * 16;
        uint4 h4, l4;
        pack8h(wi, h4, l4);
        *(uint4*)(g_W0Hi + base) = h4; *(uint4*)(g_W0Lo + base) = l4;
        pack8h(ws, h4, l4);
        *(uint4*)(g_WsHi + base) = h4; *(uint4*)(g_WsLo + base) = l4;
    }
    for (size_t i = idx; i < (size_t)131072; i += str) {
        int kg = (int)(i & 127), np = (int)((i >> 7) & 127), dt = (int)(i >> 14);
        float w[8];
#pragma unroll
        for (int e = 0; e < 8; e++) w[e] = Wfc[(size_t)(dt * 128 + np) * 1024 + kg * 8 + e];
        size_t base = (size_t)dt * FCDP + (size_t)(kg >> 3) * ACHP + np * 144 + (kg & 7) * 16;
        uint4 h4, l4;
        pack8h(w, h4, l4);
        *(uint4*)(g_FcHi + base) = h4; *(uint4*)(g_FcLo + base) = l4;
    }
    for (size_t i = idx; i < (size_t)16384; i += str) {
        int kg = (int)(i & 127), m = (int)(i >> 7);
        float v[8];
#pragma unroll
        for (int e = 0; e < 8; e++) v[e] = hT[(size_t)m * 1024 + kg * 8 + e];
        size_t base = (size_t)(kg >> 3) * ACHP + m * 144 + (kg & 7) * 16;
        uint4 h4, l4;
        pack8h(v, h4, l4);
        *(uint4*)(g_Ahi + base) = h4; *(uint4*)(g_Alo + base) = l4;
    }
    for (size_t i = idx; i < (size_t)4096; i += str) {
        int np = (int)(i & 31), cta = (int)(i >> 5);
        int row = (np & 3) * 1024 + cta * 8 + (np >> 2);
        g_biasP[i] = bih[row] + bhh[row];
    }
}

// ------------------------- fused persistent kernel -------------------------
// LSTM smem: [0,73728) Whi | [73728,147456) Wlo(scaled) |
//   [147456,184320) per-warp A staging: 8 x {2 bufs x 2304 (Ahi only)}
//   [184320) bias 128B | [184448) item slot
// FC smem (after conversion): 2 buffers x 73728 {Ahi|Alo|Bhi|Blo} in [0,147456)
#define W_LO   73728
#define ABUF   147456
#define WBUF   4608               // per-warp staging (2 x 2304)
#define S_BIAS 184320
#define S_ITEM 184448
#define SM_ALL 184576

__global__ void __launch_bounds__(256, 1) lstm_fused(const float* __restrict__ bfc,
                                                     float* __restrict__ out)
{
    extern __shared__ unsigned char smem[];
    const uint32_t sb = smem_u32(smem);
    const int tid = threadIdx.x;
    const int w = tid >> 5, lane = tid & 31;
    const int g = lane >> 2, tig = lane & 3;
    const int cta = blockIdx.x;

    if (cta < NLSTM) {
        // ---------------- LSTM role ----------------
        if (tid < 32) ((float*)(smem + S_BIAS))[tid] = g_biasP[cta * 32 + tid];
        const float* biasS = (const float*)(smem + S_BIAS);

        // resident W <- W0
        {
            const unsigned char* s2 = g_W0Hi + (size_t)cta * WCTAP;
            const unsigned char* s3 = g_W0Lo + (size_t)cta * WCTAP;
            for (int i = tid; i < 4608; i += 256) cpa16(sb + i * 16, s2 + i * 16);
            for (int i = tid; i < 4608; i += 256) cpa16(sb + W_LO + i * 16, s3 + i * 16);
            CP_COMMIT();
            CP_WAIT0();
        }
        __syncthreads();

        float c[4] = {0.f, 0.f, 0.f, 0.f};
        const uint32_t mybuf = sb + ABUF + w * WBUF;
        const int rowoff = 16 * w;

        for (int t = 0; t < TT; t++) {
            if (tid == 0 && t > 0) {
                unsigned tgt = (unsigned)(NLSTM * t), v;
                do {
                    asm volatile("ld.acquire.gpu.global.u32 %0, [%1];" : "=r"(v) : "l"(&g_bar));
                    if ((int)(v - tgt) >= 0) break;
                    __nanosleep(32);
                } while (1);
            }
            __syncthreads();

            // my 16 rows of the A slot, hi ONLY (2-term split)
            const unsigned char* aH = g_Ahi + (size_t)t * SLOTP + (size_t)rowoff * 144;

            auto issueA = [&](int kc) {
                uint32_t d = mybuf + (kc & 1) * 2304;
                const unsigned char* sA = aH + (size_t)kc * ACHP;
#pragma unroll
                for (int i = 0; i < 5; i++) {
                    int e = lane + i * 32;                // 144 16B-units hi
                    if (e < 144) cpa16(d + e * 16, sA + e * 16);
                }
                CP_COMMIT();
            };

            float accH[4][4], accX[4][4];
#pragma unroll
            for (int n = 0; n < 4; n++)
#pragma unroll
                for (int q = 0; q < 4; q++) { accH[n][q] = 0.f; accX[n][q] = 0.f; }

            issueA(0); issueA(1);
            for (int kc = 0; kc < 16; kc++) {
                if (kc == 15) CP_WAIT0(); else CP_WAIT1();
                __syncwarp();
                const unsigned char* As = smem + ABUF + w * WBUF + (kc & 1) * 2304;
                const unsigned char* Bh = smem + kc * BCHP;
                const unsigned char* Bl = smem + W_LO + kc * BCHP;
                const int rb = g * 144 + tig * 4;
#pragma unroll
                for (int ks = 0; ks < 4; ks++) {
                    const int ao = rb + ks * 32;
                    uint32_t ah[4];
                    ah[0] = *(const uint32_t*)(As + ao);
                    ah[1] = *(const uint32_t*)(As + ao + 1152);
                    ah[2] = *(const uint32_t*)(As + ao + 16);
                    ah[3] = *(const uint32_t*)(As + ao + 1168);
#pragma unroll
                    for (int nt = 0; nt < 4; nt++) {
                        const int bo = (8 * nt + g) * 144 + tig * 4 + ks * 32;
                        uint32_t bh0 = *(const uint32_t*)(Bh + bo);
                        uint32_t bh1 = *(const uint32_t*)(Bh + bo + 16);
                        uint32_t bl0 = *(const uint32_t*)(Bl + bo);
                        uint32_t bl1 = *(const uint32_t*)(Bl + bo + 16);
                        hmma(accH[nt], ah, bh0, bh1);       // xh * wh
                        hmma(accX[nt], ah, bl0, bl1);       // xh * wl  (scaled 2^11)
                    }
                }
                __syncwarp();
                if (kc + 2 < 16) issueA(kc + 2);
            }

            if (t == 0) {
                __syncthreads();   // all warps done with W0 before swap
                const unsigned char* s2 = g_WsHi + (size_t)cta * WCTAP;
                const unsigned char* s3 = g_WsLo + (size_t)cta * WCTAP;
                for (int i = tid; i < 4608; i += 256) cpa16(sb + i * 16, s2 + i * 16);
                for (int i = tid; i < 4608; i += 256) cpa16(sb + W_LO + i * 16, s3 + i * 16);
                CP_COMMIT();
                CP_WAIT0();
                __syncthreads();
            }

            // epilogue: merge scaled residual, activations, dual store (hi + scaled lo)
            const int parity = lane & 1;
#pragma unroll
            for (int nt = 0; nt < 4; nt++) {
                float d0 = accH[nt][0] + accX[nt][0] * RINV;
                float d1 = accH[nt][1] + accX[nt][1] * RINV;
                float d2 = accH[nt][2] + accX[nt][2] * RINV;
                float d3 = accH[nt][3] + accX[nt][3] * RINV;
                float s0 = parity ? d0 : d2;
                float s1 = parity ? d1 : d3;
                float r0 = __shfl_xor_sync(0xffffffffu, s0, 1);
                float r1 = __shfl_xor_sync(0xffffffffu, s1, 1);
                float ivr, fvr, gvr, ovr; int m;
                if (!parity) { ivr = d0; fvr = d1; gvr = r0; ovr = r1; m = 16 * w + g; }
                else         { ivr = r0; fvr = r1; gvr = d2; ovr = d3; m = 16 * w + g + 8; }
                int u = 2 * nt + (tig >> 1);
                const float* bb = biasS + 4 * u;
                float iv = sigf(ivr + bb[0]);
                float fv = sigf(fvr + bb[1]);
                float gv = tanhx(gvr + bb[2]);
                float ov = sigf(ovr + bb[3]);
                c[nt] = fv * c[nt] + iv * gv;
                float h = ov * tanhx(c[nt]);
                int j = cta * 8 + u;
                size_t off = (size_t)(t + 1) * SLOTP + (size_t)(j >> 6) * ACHP
                           + (size_t)m * 144 + (j & 63) * 2;
                __half hh = __float2half(h);
                *(__half*)(g_Ahi + off) = hh;
                *(__half*)(g_Alo + off) = __float2half((h - __half2float(hh)) * RSCALE);
            }
            __syncthreads();
            if (tid == 0)
                asm volatile("red.release.gpu.global.add.u32 [%0], %1;" :: "l"(&g_bar), "r"(1u) : "memory");
        }
        __syncthreads();
    }

    // ---------------- FC worker role (full 3-term fp16, scaled residuals) ----------------
    unsigned* itemp = (unsigned*)(smem + S_ITEM);
    for (;;) {
        __syncthreads();
        if (tid == 0) *itemp = atomicAdd(&g_fcitem, 1u);
        __syncthreads();
        unsigned item = *itemp;
        if (item >= 2048u) break;
        int s = (int)(item >> 3), dt = (int)(item & 7);

        if (tid == 0) {
            unsigned tgt = (unsigned)(NLSTM * (s + 1)), v;
            do {
                asm volatile("ld.acquire.gpu.global.u32 %0, [%1];" : "=r"(v) : "l"(&g_bar));
                if ((int)(v - tgt) >= 0) break;
                __nanosleep(64);
            } while (1);
        }
        __syncthreads();

        const unsigned char* aH = g_Ahi + (size_t)(s + 1) * SLOTP;
        const unsigned char* aL = g_Alo + (size_t)(s + 1) * SLOTP;
        const unsigned char* bH = g_FcHi + (size_t)dt * FCDP;
        const unsigned char* bL = g_FcLo + (size_t)dt * FCDP;

        auto issueF = [&](int kc) {
            uint32_t d = sb + (kc & 1) * 73728;
            const unsigned char* s0 = aH + (size_t)kc * ACHP;
            const unsigned char* s1 = aL + (size_t)kc * ACHP;
            const unsigned char* s2 = bH + (size_t)kc * ACHP;
            const unsigned char* s3 = bL + (size_t)kc * ACHP;
            for (int i = tid; i < 1152; i += 256) cpa16(d + i * 16, s0 + i * 16);
            for (int i = tid; i < 1152; i += 256) cpa16(d + 18432 + i * 16, s1 + i * 16);
            for (int i = tid; i < 1152; i += 256) cpa16(d + 36864 + i * 16, s2 + i * 16);
            for (int i = tid; i < 1152; i += 256) cpa16(d + 55296 + i * 16, s3 + i * 16);
            CP_COMMIT();
        };

        float accH[16][4], accX[16][4];
#pragma unroll
        for (int n = 0; n < 16; n++)
#pragma unroll
            for (int q = 0; q < 4; q++) { accH[n][q] = 0.f; accX[n][q] = 0.f; }

        issueF(0); issueF(1);
        for (int kc = 0; kc < 16; kc++) {
            if (kc == 15) CP_WAIT0(); else CP_WAIT1();
            __syncthreads();
            const unsigned char* As = smem + (kc & 1) * 73728;
            const unsigned char* Al = As + 18432;
            const unsigned char* Bh = As + 36864;
            const unsigned char* Bl = As + 55296;
            const int rb = (16 * w + g) * 144 + tig * 4;
#pragma unroll
            for (int ks = 0; ks < 4; ks++) {
                const int ao = rb + ks * 32;
                uint32_t ah[4], al4[4];
                ah[0] = *(const uint32_t*)(As + ao);
                ah[1] = *(const uint32_t*)(As + ao + 1152);
                ah[2] = *(const uint32_t*)(As + ao + 16);
                ah[3] = *(const uint32_t*)(As + ao + 1168);
                al4[0] = *(const uint32_t*)(Al + ao);
                al4[1] = *(const uint32_t*)(Al + ao + 1152);
                al4[2] = *(const uint32_t*)(Al + ao + 16);
                al4[3] = *(const uint32_t*)(Al + ao + 1168);
#pragma unroll
                for (int nt = 0; nt < 16; nt++) {
                    const int bo = (8 * nt + g) * 144 + tig * 4 + ks * 32;
                    uint32_t bh0 = *(const uint32_t*)(Bh + bo);
                    uint32_t bh1 = *(const uint32_t*)(Bh + bo + 16);
                    uint32_t bl0 = *(const uint32_t*)(Bl + bo);
                    uint32_t bl1 = *(const uint32_t*)(Bl + bo + 16);
                    hmma(accH[nt], ah, bh0, bh1);   // xh*wh
                    hmma(accX[nt], al4, bh0, bh1);  // xl*wh  (scaled 2^11)
                    hmma(accX[nt], ah, bl0, bl1);   // xh*wl  (scaled 2^11)
                }
            }
            __syncthreads();
            if (kc + 2 < 16) issueF(kc + 2);
        }

#pragma unroll
        for (int nt = 0; nt < 16; nt++) {
            int d = dt * 128 + 8 * nt + 2 * tig;
            float2 bb = *(const float2*)(bfc + d);
            int n0 = 16 * w + g;
            float2 v0 = make_float2(accH[nt][0] + accX[nt][0] * RINV + bb.x,
                                    accH[nt][1] + accX[nt][1] * RINV + bb.y);
            float2 v1 = make_float2(accH[nt][2] + accX[nt][2] * RINV + bb.x,
                                    accH[nt][3] + accX[nt][3] * RINV + bb.y);
            *(float2*)(out + ((size_t)n0 * TT + s) * 1024 + d) = v0;
            *(float2*)(out + ((size_t)(n0 + 8) * TT + s) * 1024 + d) = v1;
        }
    }
}

// ------------------------- launch -------------------------
extern "C" void kernel_launch(void* const* d_in, const int* in_sizes, int n_in,
                              void* d_out, int out_size)
{
    const float* hT  = (const float*)d_in[0];
    const float* Wih = (const float*)d_in[1];
    const float* Whh = (const float*)d_in[2];
    const float* bih = (const float*)d_in[3];
    const float* bhh = (const float*)d_in[4];
    const float* Wfc = (const float*)d_in[5];
    const float* bfc = (const float*)d_in[6];
    float* out = (float*)d_out;

    static int total = 0;
    if (total == 0) {
        int smc = 148;
        if (cudaDeviceGetAttribute(&smc, cudaDevAttrMultiProcessorCount, 0) != cudaSuccess)
            smc = 148;
        total = smc < 129 ? 129 : (smc > 192 ? 192 : smc);
        cudaFuncSetAttribute(lstm_fused, cudaFuncAttributeMaxDynamicSharedMemorySize, SM_ALL);
    }

    prep<<<1024, 256>>>(hT, Wih, Whh, bih, bhh, Wfc);
    lstm_fused<<<total, 256, SM_ALL>>>(bfc, out);
}

// round 16
// speedup vs baseline: 1.4647x; 1.4647x over previous
#include <cuda_runtime.h>
#include <cuda_fp16.h>
#include <cstdint>

#define TT 256
#define NLSTM 128
#define ACHP 18432                 // padded A chunk: 128 rows x 144B
#define SLOTP (16*ACHP)            // per A slot per matrix
#define BCHP 4608                  // padded W chunk: 32 rows x 144B
#define WCTAP (16*BCHP)            // 73728 per CTA per matrix
#define FCCH 9216                  // FC W chunk: 64 rows x 144B
#define FCDP (16*FCCH)             // FC W d-tile (64 d) per matrix
#define RSCALE 2048.0f             // residual scale 2^11 (exact)
#define RINV (1.0f/2048.0f)

// ------------------------- device scratch -------------------------
__device__ __align__(128) unsigned char g_Ahi[(size_t)(TT+1)*SLOTP];
__device__ __align__(128) unsigned char g_Alo[(size_t)(TT+1)*SLOTP];   // scaled resid (FC only)
__device__ __align__(128) unsigned char g_WsHi[(size_t)NLSTM*WCTAP];
__device__ __align__(128) unsigned char g_WsLo[(size_t)NLSTM*WCTAP];   // scaled resid
__device__ __align__(128) unsigned char g_W0Hi[(size_t)NLSTM*WCTAP];
__device__ __align__(128) unsigned char g_W0Lo[(size_t)NLSTM*WCTAP];
__device__ __align__(128) unsigned char g_FcHi[(size_t)16*FCDP];
__device__ __align__(128) unsigned char g_FcLo[(size_t)16*FCDP];
__device__ float g_biasP[NLSTM*32];
__device__ unsigned g_bar;
__device__ unsigned g_fcitem;

// ------------------------- helpers -------------------------
__device__ __forceinline__ uint32_t smem_u32(const void* p) {
    uint32_t a;
    asm("{ .reg .u64 t; cvta.to.shared.u64 t, %1; cvt.u32.u64 %0, t; }" : "=r"(a) : "l"(p));
    return a;
}
__device__ __forceinline__ void cpa16(uint32_t dst, const void* src) {
    asm volatile("cp.async.cg.shared.global [%0], [%1], 16;" :: "r"(dst), "l"(src));
}
#define CP_COMMIT() asm volatile("cp.async.commit_group;")
#define CP_WAIT1()  asm volatile("cp.async.wait_group 1;")
#define CP_WAIT0()  asm volatile("cp.async.wait_group 0;")

__device__ __forceinline__ void hmma(float* c, const uint32_t* a, uint32_t b0, uint32_t b1) {
    asm volatile(
        "mma.sync.aligned.m16n8k16.row.col.f32.f16.f16.f32 "
        "{%0,%1,%2,%3}, {%4,%5,%6,%7}, {%8,%9}, {%0,%1,%2,%3};"
        : "+f"(c[0]), "+f"(c[1]), "+f"(c[2]), "+f"(c[3])
        : "r"(a[0]), "r"(a[1]), "r"(a[2]), "r"(a[3]), "r"(b0), "r"(b1));
}
__device__ __forceinline__ float sigf(float x)  { return 1.0f / (1.0f + __expf(-x)); }
__device__ __forceinline__ float tanhx(float x) { return 2.0f / (1.0f + __expf(-2.0f * x)) - 1.0f; }

// fp16 split: hi = fp16(v), lo = fp16((v - hi) * 2^11)
__device__ __forceinline__ void pack8h(const float* v, uint4& hi, uint4& lo) {
    uint32_t* hw = (uint32_t*)&hi; uint32_t* lw = (uint32_t*)&lo;
#pragma unroll
    for (int q = 0; q < 4; q++) {
        __half h0 = __float2half(v[2*q]), h1 = __float2half(v[2*q+1]);
        __half l0 = __float2half((v[2*q]   - __half2float(h0)) * RSCALE);
        __half l1 = __float2half((v[2*q+1] - __half2float(h1)) * RSCALE);
        __half2 ph = __halves2half2(h0, h1), pl = __halves2half2(l0, l1);
        hw[q] = *(uint32_t*)&ph; lw[q] = *(uint32_t*)&pl;
    }
}

// ------------------------- prep -------------------------
__global__ void prep(const float* __restrict__ hT, const float* __restrict__ Wih,
                     const float* __restrict__ Whh, const float* __restrict__ bih,
                     const float* __restrict__ bhh, const float* __restrict__ Wfc)
{
    size_t idx = (size_t)blockIdx.x * blockDim.x + threadIdx.x;
    size_t str = (size_t)gridDim.x * blockDim.x;
    if (idx == 0) { g_bar = 0; g_fcitem = 0; }

    for (size_t i = idx; i < (size_t)524288; i += str) {
        int kg = (int)(i & 127), np = (int)((i >> 7) & 31), cta = (int)(i >> 12);
        int row = (np & 3) * 1024 + cta * 8 + (np >> 2);
        int k = kg * 8;
        float wi[8], ws[8];
#pragma unroll
        for (int e = 0; e < 8; e++) {
            float a = Wih[(size_t)row * 1024 + k + e];
            wi[e] = a; ws[e] = a + Whh[(size_t)row * 1024 + k + e];
        }
        size_t base = (size_t)cta * WCTAP + (size_t)(kg >> 3) * BCHP + np * 144 + (kg & 7) * 16;
        uint4 h4, l4;
        pack8h(wi, h4, l4);
        *(uint4*)(g_W0Hi + base) = h4; *(uint4*)(g_W0Lo + base) = l4;
        pack8h(ws, h4, l4);
        *(uint4*)(g_WsHi + base) = h4; *(uint4*)(g_WsLo + base) = l4;
    }
    // fc weights: dt(16) x np(64) x kg(128)
    for (size_t i = idx; i < (size_t)131072; i += str) {
        int kg = (int)(i & 127), np = (int)((i >> 7) & 63), dt = (int)(i >> 13);
        float w[8];
#pragma unroll
        for (int e = 0; e < 8; e++) w[e] = Wfc[(size_t)(dt * 64 + np) * 1024 + kg * 8 + e];
        size_t base = (size_t)dt * FCDP + (size_t)(kg >> 3) * FCCH + np * 144 + (kg & 7) * 16;
        uint4 h4, l4;
        pack8h(w, h4, l4);
        *(uint4*)(g_FcHi + base) = h4; *(uint4*)(g_FcLo + base) = l4;
    }
    for (size_t i = idx; i < (size_t)16384; i += str) {
        int kg = (int)(i & 127), m = (int)(i >> 7);
        float v[8];
#pragma unroll
        for (int e = 0; e < 8; e++) v[e] = hT[(size_t)m * 1024 + kg * 8 + e];
        size_t base = (size_t)(kg >> 3) * ACHP + m * 144 + (kg & 7) * 16;
        uint4 h4, l4;
        pack8h(v, h4, l4);
        *(uint4*)(g_Ahi + base) = h4; *(uint4*)(g_Alo + base) = l4;
    }
    for (size_t i = idx; i < (size_t)4096; i += str) {
        int np = (int)(i & 31), cta = (int)(i >> 5);
        int row = (np & 3) * 1024 + cta * 8 + (np >> 2);
        g_biasP[i] = bih[row] + bhh[row];
    }
}

// ------------------------- fused persistent kernel -------------------------
// LSTM smem: [0,73728) Whi | [73728,147456) Wlo(scaled) |
//   [147456,184320) per-warp A staging: 8 x {2 bufs x 2304 (Ahi only)}
//   [184320) bias 128B | [184448) item slot
// FC smem (after conversion): 2 buffers x 55296 {Ahi 18432|Alo 18432|Bhi 9216|Blo 9216}
#define W_LO   73728
#define ABUF   147456
#define WBUF   4608               // per-warp staging (2 x 2304)
#define S_BIAS 184320
#define S_ITEM 184448
#define SM_ALL 184576
#define FBUF   55296

__global__ void __launch_bounds__(256, 1) lstm_fused(const float* __restrict__ bfc,
                                                     float* __restrict__ out)
{
    extern __shared__ unsigned char smem[];
    const uint32_t sb = smem_u32(smem);
    const int tid = threadIdx.x;
    const int w = tid >> 5, lane = tid & 31;
    const int g = lane >> 2, tig = lane & 3;
    const int cta = blockIdx.x;

    if (cta < NLSTM) {
        // ---------------- LSTM role ----------------
        if (tid < 32) ((float*)(smem + S_BIAS))[tid] = g_biasP[cta * 32 + tid];
        const float* biasS = (const float*)(smem + S_BIAS);

        // resident W <- W0
        {
            const unsigned char* s2 = g_W0Hi + (size_t)cta * WCTAP;
            const unsigned char* s3 = g_W0Lo + (size_t)cta * WCTAP;
            for (int i = tid; i < 4608; i += 256) cpa16(sb + i * 16, s2 + i * 16);
            for (int i = tid; i < 4608; i += 256) cpa16(sb + W_LO + i * 16, s3 + i * 16);
            CP_COMMIT();
            CP_WAIT0();
        }
        __syncthreads();

        float c[4] = {0.f, 0.f, 0.f, 0.f};
        const uint32_t mybuf = sb + ABUF + w * WBUF;
        const int rowoff = 16 * w;

        for (int t = 0; t < TT; t++) {
            if (tid == 0 && t > 0) {
                unsigned tgt = (unsigned)(NLSTM * t), v;
                do {
                    asm volatile("ld.acquire.gpu.global.u32 %0, [%1];" : "=r"(v) : "l"(&g_bar));
                    if ((int)(v - tgt) >= 0) break;
                    __nanosleep(32);
                } while (1);
            }
            __syncthreads();

            const unsigned char* aH = g_Ahi + (size_t)t * SLOTP + (size_t)rowoff * 144;

            auto issueA = [&](int kc) {
                uint32_t d = mybuf + (kc & 1) * 2304;
                const unsigned char* sA = aH + (size_t)kc * ACHP;
#pragma unroll
                for (int i = 0; i < 5; i++) {
                    int e = lane + i * 32;
                    if (e < 144) cpa16(d + e * 16, sA + e * 16);
                }
                CP_COMMIT();
            };

            float accH[4][4], accX[4][4];
#pragma unroll
            for (int n = 0; n < 4; n++)
#pragma unroll
                for (int q = 0; q < 4; q++) { accH[n][q] = 0.f; accX[n][q] = 0.f; }

            issueA(0); issueA(1);
            for (int kc = 0; kc < 16; kc++) {
                if (kc == 15) CP_WAIT0(); else CP_WAIT1();
                __syncwarp();
                const unsigned char* As = smem + ABUF + w * WBUF + (kc & 1) * 2304;
                const unsigned char* Bh = smem + kc * BCHP;
                const unsigned char* Bl = smem + W_LO + kc * BCHP;
                const int rb = g * 144 + tig * 4;
#pragma unroll
                for (int ks = 0; ks < 4; ks++) {
                    const int ao = rb + ks * 32;
                    uint32_t ah[4];
                    ah[0] = *(const uint32_t*)(As + ao);
                    ah[1] = *(const uint32_t*)(As + ao + 1152);
                    ah[2] = *(const uint32_t*)(As + ao + 16);
                    ah[3] = *(const uint32_t*)(As + ao + 1168);
#pragma unroll
                    for (int nt = 0; nt < 4; nt++) {
                        const int bo = (8 * nt + g) * 144 + tig * 4 + ks * 32;
                        uint32_t bh0 = *(const uint32_t*)(Bh + bo);
                        uint32_t bh1 = *(const uint32_t*)(Bh + bo + 16);
                        uint32_t bl0 = *(const uint32_t*)(Bl + bo);
                        uint32_t bl1 = *(const uint32_t*)(Bl + bo + 16);
                        hmma(accH[nt], ah, bh0, bh1);       // xh * wh
                        hmma(accX[nt], ah, bl0, bl1);       // xh * wl (scaled 2^11)
                    }
                }
                __syncwarp();
                if (kc + 2 < 16) issueA(kc + 2);
            }

            if (t == 0) {
                __syncthreads();
                const unsigned char* s2 = g_WsHi + (size_t)cta * WCTAP;
                const unsigned char* s3 = g_WsLo + (size_t)cta * WCTAP;
                for (int i = tid; i < 4608; i += 256) cpa16(sb + i * 16, s2 + i * 16);
                for (int i = tid; i < 4608; i += 256) cpa16(sb + W_LO + i * 16, s3 + i * 16);
                CP_COMMIT();
                CP_WAIT0();
                __syncthreads();
            }

            // epilogue
            const int parity = lane & 1;
#pragma unroll
            for (int nt = 0; nt < 4; nt++) {
                float d0 = accH[nt][0] + accX[nt][0] * RINV;
                float d1 = accH[nt][1] + accX[nt][1] * RINV;
                float d2 = accH[nt][2] + accX[nt][2] * RINV;
                float d3 = accH[nt][3] + accX[nt][3] * RINV;
                float s0 = parity ? d0 : d2;
                float s1 = parity ? d1 : d3;
                float r0 = __shfl_xor_sync(0xffffffffu, s0, 1);
                float r1 = __shfl_xor_sync(0xffffffffu, s1, 1);
                float ivr, fvr, gvr, ovr; int m;
                if (!parity) { ivr = d0; fvr = d1; gvr = r0; ovr = r1; m = 16 * w + g; }
                else         { ivr = r0; fvr = r1; gvr = d2; ovr = d3; m = 16 * w + g + 8; }
                int u = 2 * nt + (tig >> 1);
                const float* bb = biasS + 4 * u;
                float iv = sigf(ivr + bb[0]);
                float fv = sigf(fvr + bb[1]);
                float gv = tanhx(gvr + bb[2]);
                float ov = sigf(ovr + bb[3]);
                c[nt] = fv * c[nt] + iv * gv;
                float h = ov * tanhx(c[nt]);
                int j = cta * 8 + u;
                size_t off = (size_t)(t + 1) * SLOTP + (size_t)(j >> 6) * ACHP
                           + (size_t)m * 144 + (j & 63) * 2;
                __half hh = __float2half(h);
                *(__half*)(g_Ahi + off) = hh;
                *(__half*)(g_Alo + off) = __float2half((h - __half2float(hh)) * RSCALE);
            }
            __syncthreads();
            if (tid == 0)
                asm volatile("red.release.gpu.global.add.u32 [%0], %1;" :: "l"(&g_bar), "r"(1u) : "memory");
        }
        __syncthreads();
    }

    // ---------------- FC worker role (3-term fp16, 64-d tiles) ----------------
    unsigned* itemp = (unsigned*)(smem + S_ITEM);
    for (;;) {
        __syncthreads();
        if (tid == 0) *itemp = atomicAdd(&g_fcitem, 1u);
        __syncthreads();
        unsigned item = *itemp;
        if (item >= 4096u) break;
        int s = (int)(item >> 4), dt = (int)(item & 15);

        if (tid == 0) {
            unsigned tgt = (unsigned)(NLSTM * (s + 1)), v;
            do {
                asm volatile("ld.acquire.gpu.global.u32 %0, [%1];" : "=r"(v) : "l"(&g_bar));
                if ((int)(v - tgt) >= 0) break;
                __nanosleep(64);
            } while (1);
        }
        __syncthreads();

        const unsigned char* aH = g_Ahi + (size_t)(s + 1) * SLOTP;
        const unsigned char* aL = g_Alo + (size_t)(s + 1) * SLOTP;
        const unsigned char* bH = g_FcHi + (size_t)dt * FCDP;
        const unsigned char* bL = g_FcLo + (size_t)dt * FCDP;

        auto issueF = [&](int kc) {
            uint32_t d = sb + (kc & 1) * FBUF;
            const unsigned char* s0 = aH + (size_t)kc * ACHP;
            const unsigned char* s1 = aL + (size_t)kc * ACHP;
            const unsigned char* s2 = bH + (size_t)kc * FCCH;
            const unsigned char* s3 = bL + (size_t)kc * FCCH;
            for (int i = tid; i < 1152; i += 256) cpa16(d + i * 16, s0 + i * 16);
            for (int i = tid; i < 1152; i += 256) cpa16(d + 18432 + i * 16, s1 + i * 16);
            for (int i = tid; i < 576; i += 256) cpa16(d + 36864 + i * 16, s2 + i * 16);
            for (int i = tid; i < 576; i += 256) cpa16(d + 46080 + i * 16, s3 + i * 16);
            CP_COMMIT();
        };

        float accH[8][4], accX[8][4];
#pragma unroll
        for (int n = 0; n < 8; n++)
#pragma unroll
            for (int q = 0; q < 4; q++) { accH[n][q] = 0.f; accX[n][q] = 0.f; }

        issueF(0); issueF(1);
        for (int kc = 0; kc < 16; kc++) {
            if (kc == 15) CP_WAIT0(); else CP_WAIT1();
            __syncthreads();
            const unsigned char* As = smem + (kc & 1) * FBUF;
            const unsigned char* Al = As + 18432;
            const unsigned char* Bh = As + 36864;
            const unsigned char* Bl = As + 46080;
            const int rb = (16 * w + g) * 144 + tig * 4;
#pragma unroll
            for (int ks = 0; ks < 4; ks++) {
                const int ao = rb + ks * 32;
                uint32_t ah[4], al4[4];
                ah[0] = *(const uint32_t*)(As + ao);
                ah[1] = *(const uint32_t*)(As + ao + 1152);
                ah[2] = *(const uint32_t*)(As + ao + 16);
                ah[3] = *(const uint32_t*)(As + ao + 1168);
                al4[0] = *(const uint32_t*)(Al + ao);
                al4[1] = *(const uint32_t*)(Al + ao + 1152);
                al4[2] = *(const uint32_t*)(Al + ao + 16);
                al4[3] = *(const uint32_t*)(Al + ao + 1168);
#pragma unroll
                for (int nt = 0; nt < 8; nt++) {
                    const int bo = (8 * nt + g) * 144 + tig * 4 + ks * 32;
                    uint32_t bh0 = *(const uint32_t*)(Bh + bo);
                    uint32_t bh1 = *(const uint32_t*)(Bh + bo + 16);
                    uint32_t bl0 = *(const uint32_t*)(Bl + bo);
                    uint32_t bl1 = *(const uint32_t*)(Bl + bo + 16);
                    hmma(accH[nt], ah, bh0, bh1);   // xh*wh
                    hmma(accX[nt], al4, bh0, bh1);  // xl*wh (scaled)
                    hmma(accX[nt], ah, bl0, bl1);   // xh*wl (scaled)
                }
            }
            __syncthreads();
            if (kc + 2 < 16) issueF(kc + 2);
        }

#pragma unroll
        for (int nt = 0; nt < 8; nt++) {
            int d = dt * 64 + 8 * nt + 2 * tig;
            float2 bb = *(const float2*)(bfc + d);
            int n0 = 16 * w + g;
            float2 v0 = make_float2(accH[nt][0] + accX[nt][0] * RINV + bb.x,
                                    accH[nt][1] + accX[nt][1] * RINV + bb.y);
            float2 v1 = make_float2(accH[nt][2] + accX[nt][2] * RINV + bb.x,
                                    accH[nt][3] + accX[nt][3] * RINV + bb.y);
            *(float2*)(out + ((size_t)n0 * TT + s) * 1024 + d) = v0;
            *(float2*)(out + ((size_t)(n0 + 8) * TT + s) * 1024 + d) = v1;
        }
    }
}

// ------------------------- launch -------------------------
extern "C" void kernel_launch(void* const* d_in, const int* in_sizes, int n_in,
                              void* d_out, int out_size)
{
    const float* hT  = (const float*)d_in[0];
    const float* Wih = (const float*)d_in[1];
    const float* Whh = (const float*)d_in[2];
    const float* bih = (const float*)d_in[3];
    const float* bhh = (const float*)d_in[4];
    const float* Wfc = (const float*)d_in[5];
    const float* bfc = (const float*)d_in[6];
    float* out = (float*)d_out;

    static int total = 0;
    if (total == 0) {
        int smc = 148;
        if (cudaDeviceGetAttribute(&smc, cudaDevAttrMultiProcessorCount, 0) != cudaSuccess)
            smc = 148;
        total = smc < 129 ? 129 : (smc > 192 ? 192 : smc);
        cudaFuncSetAttribute(lstm_fused, cudaFuncAttributeMaxDynamicSharedMemorySize, SM_ALL);
    }

    prep<<<1024, 256>>>(hT, Wih, Whh, bih, bhh, Wfc);
    lstm_fused<<<total, 256, SM_ALL>>>(bfc, out);
}

// round 17
// speedup vs baseline: 1.4773x; 1.0086x over previous
#include <cuda_runtime.h>
#include <cuda_fp16.h>
#include <cstdint>

#define TT 256
#define NLSTM 128
#define ACHP 18432                 // padded A chunk: 128 rows x 144B
#define SLOTP (16*ACHP)            // per A slot per matrix
#define BCHP 4608                  // padded W chunk: 32 rows x 144B
#define WCTAP (16*BCHP)            // 73728 per CTA per matrix
#define FCCH 9216                  // FC W chunk: 64 rows x 144B
#define FCDP (16*FCCH)             // FC W d-tile (64 d) per matrix
#define RSCALE 2048.0f             // residual scale 2^11 (exact)
#define RINV (1.0f/2048.0f)

// ------------------------- device scratch -------------------------
__device__ __align__(128) unsigned char g_Ahi[(size_t)(TT+1)*SLOTP];
__device__ __align__(128) unsigned char g_Alo[(size_t)(TT+1)*SLOTP];   // scaled resid (FC only)
__device__ __align__(128) unsigned char g_WsHi[(size_t)NLSTM*WCTAP];
__device__ __align__(128) unsigned char g_WsLo[(size_t)NLSTM*WCTAP];   // scaled resid
__device__ __align__(128) unsigned char g_W0Hi[(size_t)NLSTM*WCTAP];
__device__ __align__(128) unsigned char g_W0Lo[(size_t)NLSTM*WCTAP];
__device__ __align__(128) unsigned char g_FcHi[(size_t)16*FCDP];
__device__ __align__(128) unsigned char g_FcLo[(size_t)16*FCDP];
__device__ float g_biasP[NLSTM*32];
__device__ unsigned g_bar;
__device__ unsigned g_fcitem;

// ------------------------- helpers -------------------------
__device__ __forceinline__ uint32_t smem_u32(const void* p) {
    uint32_t a;
    asm("{ .reg .u64 t; cvta.to.shared.u64 t, %1; cvt.u32.u64 %0, t; }" : "=r"(a) : "l"(p));
    return a;
}
__device__ __forceinline__ void cpa16(uint32_t dst, const void* src) {
    asm volatile("cp.async.cg.shared.global [%0], [%1], 16;" :: "r"(dst), "l"(src));
}
#define CP_COMMIT() asm volatile("cp.async.commit_group;")
#define CP_WAIT3()  asm volatile("cp.async.wait_group 3;")
#define CP_WAIT2()  asm volatile("cp.async.wait_group 2;")
#define CP_WAIT1()  asm volatile("cp.async.wait_group 1;")
#define CP_WAIT0()  asm volatile("cp.async.wait_group 0;")

__device__ __forceinline__ void hmma(float* c, const uint32_t* a, uint32_t b0, uint32_t b1) {
    asm volatile(
        "mma.sync.aligned.m16n8k16.row.col.f32.f16.f16.f32 "
        "{%0,%1,%2,%3}, {%4,%5,%6,%7}, {%8,%9}, {%0,%1,%2,%3};"
        : "+f"(c[0]), "+f"(c[1]), "+f"(c[2]), "+f"(c[3])
        : "r"(a[0]), "r"(a[1]), "r"(a[2]), "r"(a[3]), "r"(b0), "r"(b1));
}
__device__ __forceinline__ float sigf(float x)  { return 1.0f / (1.0f + __expf(-x)); }
__device__ __forceinline__ float tanhx(float x) { return 2.0f / (1.0f + __expf(-2.0f * x)) - 1.0f; }

// fp16 split: hi = fp16(v), lo = fp16((v - hi) * 2^11)
__device__ __forceinline__ void pack8h(const float* v, uint4& hi, uint4& lo) {
    uint32_t* hw = (uint32_t*)&hi; uint32_t* lw = (uint32_t*)&lo;
#pragma unroll
    for (int q = 0; q < 4; q++) {
        __half h0 = __float2half(v[2*q]), h1 = __float2half(v[2*q+1]);
        __half l0 = __float2half((v[2*q]   - __half2float(h0)) * RSCALE);
        __half l1 = __float2half((v[2*q+1] - __half2float(h1)) * RSCALE);
        __half2 ph = __halves2half2(h0, h1), pl = __halves2half2(l0, l1);
        hw[q] = *(uint32_t*)&ph; lw[q] = *(uint32_t*)&pl;
    }
}

// ------------------------- prep -------------------------
__global__ void prep(const float* __restrict__ hT, const float* __restrict__ Wih,
                     const float* __restrict__ Whh, const float* __restrict__ bih,
                     const float* __restrict__ bhh, const float* __restrict__ Wfc)
{
    size_t idx = (size_t)blockIdx.x * blockDim.x + threadIdx.x;
    size_t str = (size_t)gridDim.x * blockDim.x;
    if (idx == 0) { g_bar = 0; g_fcitem = 0; }

    for (size_t i = idx; i < (size_t)524288; i += str) {
        int kg = (int)(i & 127), np = (int)((i >> 7) & 31), cta = (int)(i >> 12);
        int row = (np & 3) * 1024 + cta * 8 + (np >> 2);
        int k = kg * 8;
        float wi[8], ws[8];
#pragma unroll
        for (int e = 0; e < 8; e++) {
            float a = Wih[(size_t)row * 1024 + k + e];
            wi[e] = a; ws[e] = a + Whh[(size_t)row * 1024 + k + e];
        }
        size_t base = (size_t)cta * WCTAP + (size_t)(kg >> 3) * BCHP + np * 144 + (kg & 7) * 16;
        uint4 h4, l4;
        pack8h(wi, h4, l4);
        *(uint4*)(g_W0Hi + base) = h4; *(uint4*)(g_W0Lo + base) = l4;
        pack8h(ws, h4, l4);
        *(uint4*)(g_WsHi + base) = h4; *(uint4*)(g_WsLo + base) = l4;
    }
    // fc weights: dt(16) x np(64) x kg(128)
    for (size_t i = idx; i < (size_t)131072; i += str) {
        int kg = (int)(i & 127), np = (int)((i >> 7) & 63), dt = (int)(i >> 13);
        float w[8];
#pragma unroll
        for (int e = 0; e < 8; e++) w[e] = Wfc[(size_t)(dt * 64 + np) * 1024 + kg * 8 + e];
        size_t base = (size_t)dt * FCDP + (size_t)(kg >> 3) * FCCH + np * 144 + (kg & 7) * 16;
        uint4 h4, l4;
        pack8h(w, h4, l4);
        *(uint4*)(g_FcHi + base) = h4; *(uint4*)(g_FcLo + base) = l4;
    }
    for (size_t i = idx; i < (size_t)16384; i += str) {
        int kg = (int)(i & 127), m = (int)(i >> 7);
        float v[8];
#pragma unroll
        for (int e = 0; e < 8; e++) v[e] = hT[(size_t)m * 1024 + kg * 8 + e];
        size_t base = (size_t)(kg >> 3) * ACHP + m * 144 + (kg & 7) * 16;
        uint4 h4, l4;
        pack8h(v, h4, l4);
        *(uint4*)(g_Ahi + base) = h4; *(uint4*)(g_Alo + base) = l4;
    }
    for (size_t i = idx; i < (size_t)4096; i += str) {
        int np = (int)(i & 31), cta = (int)(i >> 5);
        int row = (np & 3) * 1024 + cta * 8 + (np >> 2);
        g_biasP[i] = bih[row] + bhh[row];
    }
}

// ------------------------- fused persistent kernel -------------------------
// LSTM smem: [0,73728) Whi | [73728,147456) Wlo(scaled) |
//   [147456,221184) per-warp A staging: 8 warps x {4 bufs x 2304 (Ahi only)}
//   [221184) bias 128B | [221312) item slot
// FC smem (after conversion): 2 buffers x 55296 {Ahi 18432|Alo 18432|Bhi 9216|Blo 9216}
#define W_LO   73728
#define ABUF   147456
#define WBUF   9216               // per-warp staging (4 x 2304)
#define S_BIAS 221184
#define S_ITEM 221312
#define SM_ALL 221440
#define FBUF   55296

__global__ void __launch_bounds__(256, 1) lstm_fused(const float* __restrict__ bfc,
                                                     float* __restrict__ out)
{
    extern __shared__ unsigned char smem[];
    const uint32_t sb = smem_u32(smem);
    const int tid = threadIdx.x;
    const int w = tid >> 5, lane = tid & 31;
    const int g = lane >> 2, tig = lane & 3;
    const int cta = blockIdx.x;

    if (cta < NLSTM) {
        // ---------------- LSTM role ----------------
        if (tid < 32) ((float*)(smem + S_BIAS))[tid] = g_biasP[cta * 32 + tid];
        const float* biasS = (const float*)(smem + S_BIAS);

        // resident W <- W0
        {
            const unsigned char* s2 = g_W0Hi + (size_t)cta * WCTAP;
            const unsigned char* s3 = g_W0Lo + (size_t)cta * WCTAP;
            for (int i = tid; i < 4608; i += 256) cpa16(sb + i * 16, s2 + i * 16);
            for (int i = tid; i < 4608; i += 256) cpa16(sb + W_LO + i * 16, s3 + i * 16);
            CP_COMMIT();
            CP_WAIT0();
        }
        __syncthreads();

        float c[4] = {0.f, 0.f, 0.f, 0.f};
        const uint32_t mybuf = sb + ABUF + w * WBUF;
        const int rowoff = 16 * w;

        for (int t = 0; t < TT; t++) {
            if (tid == 0 && t > 0) {
                unsigned tgt = (unsigned)(NLSTM * t), v;
                do {
                    asm volatile("ld.acquire.gpu.global.u32 %0, [%1];" : "=r"(v) : "l"(&g_bar));
                    if ((int)(v - tgt) >= 0) break;
                    __nanosleep(32);
                } while (1);
            }
            __syncthreads();

            const unsigned char* aH = g_Ahi + (size_t)t * SLOTP + (size_t)rowoff * 144;

            auto issueA = [&](int kc) {
                uint32_t d = mybuf + (kc & 3) * 2304;
                const unsigned char* sA = aH + (size_t)kc * ACHP;
#pragma unroll
                for (int i = 0; i < 5; i++) {
                    int e = lane + i * 32;
                    if (e < 144) cpa16(d + e * 16, sA + e * 16);
                }
                CP_COMMIT();
            };

            float accH[4][4], accX[4][4];
#pragma unroll
            for (int n = 0; n < 4; n++)
#pragma unroll
                for (int q = 0; q < 4; q++) { accH[n][q] = 0.f; accX[n][q] = 0.f; }

            issueA(0); issueA(1); issueA(2); issueA(3);
            for (int kc = 0; kc < 16; kc++) {
                // depth-4 pipeline: pending groups = min(15,kc+3) - kc + 1 after
                // waiting; need group kc complete
                if (kc <= 12)      CP_WAIT3();
                else if (kc == 13) CP_WAIT2();
                else if (kc == 14) CP_WAIT1();
                else               CP_WAIT0();
                __syncwarp();
                const unsigned char* As = smem + ABUF + w * WBUF + (kc & 3) * 2304;
                const unsigned char* Bh = smem + kc * BCHP;
                const unsigned char* Bl = smem + W_LO + kc * BCHP;
                const int rb = g * 144 + tig * 4;
#pragma unroll
                for (int ks = 0; ks < 4; ks++) {
                    const int ao = rb + ks * 32;
                    uint32_t ah[4];
                    ah[0] = *(const uint32_t*)(As + ao);
                    ah[1] = *(const uint32_t*)(As + ao + 1152);
                    ah[2] = *(const uint32_t*)(As + ao + 16);
                    ah[3] = *(const uint32_t*)(As + ao + 1168);
#pragma unroll
                    for (int nt = 0; nt < 4; nt++) {
                        const int bo = (8 * nt + g) * 144 + tig * 4 + ks * 32;
                        uint32_t bh0 = *(const uint32_t*)(Bh + bo);
                        uint32_t bh1 = *(const uint32_t*)(Bh + bo + 16);
                        uint32_t bl0 = *(const uint32_t*)(Bl + bo);
                        uint32_t bl1 = *(const uint32_t*)(Bl + bo + 16);
                        hmma(accH[nt], ah, bh0, bh1);       // xh * wh
                        hmma(accX[nt], ah, bl0, bl1);       // xh * wl (scaled 2^11)
                    }
                }
                __syncwarp();
                if (kc + 4 < 16) issueA(kc + 4);
            }

            if (t == 0) {
                __syncthreads();
                const unsigned char* s2 = g_WsHi + (size_t)cta * WCTAP;
                const unsigned char* s3 = g_WsLo + (size_t)cta * WCTAP;
                for (int i = tid; i < 4608; i += 256) cpa16(sb + i * 16, s2 + i * 16);
                for (int i = tid; i < 4608; i += 256) cpa16(sb + W_LO + i * 16, s3 + i * 16);
                CP_COMMIT();
                CP_WAIT0();
                __syncthreads();
            }

            // epilogue
            const int parity = lane & 1;
#pragma unroll
            for (int nt = 0; nt < 4; nt++) {
                float d0 = accH[nt][0] + accX[nt][0] * RINV;
                float d1 = accH[nt][1] + accX[nt][1] * RINV;
                float d2 = accH[nt][2] + accX[nt][2] * RINV;
                float d3 = accH[nt][3] + accX[nt][3] * RINV;
                float s0 = parity ? d0 : d2;
                float s1 = parity ? d1 : d3;
                float r0 = __shfl_xor_sync(0xffffffffu, s0, 1);
                float r1 = __shfl_xor_sync(0xffffffffu, s1, 1);
                float ivr, fvr, gvr, ovr; int m;
                if (!parity) { ivr = d0; fvr = d1; gvr = r0; ovr = r1; m = 16 * w + g; }
                else         { ivr = r0; fvr = r1; gvr = d2; ovr = d3; m = 16 * w + g + 8; }
                int u = 2 * nt + (tig >> 1);
                const float* bb = biasS + 4 * u;
                float iv = sigf(ivr + bb[0]);
                float fv = sigf(fvr + bb[1]);
                float gv = tanhx(gvr + bb[2]);
                float ov = sigf(ovr + bb[3]);
                c[nt] = fv * c[nt] + iv * gv;
                float h = ov * tanhx(c[nt]);
                int j = cta * 8 + u;
                size_t off = (size_t)(t + 1) * SLOTP + (size_t)(j >> 6) * ACHP
                           + (size_t)m * 144 + (j & 63) * 2;
                __half hh = __float2half(h);
                *(__half*)(g_Ahi + off) = hh;
                *(__half*)(g_Alo + off) = __float2half((h - __half2float(hh)) * RSCALE);
            }
            __syncthreads();
            if (tid == 0)
                asm volatile("red.release.gpu.global.add.u32 [%0], %1;" :: "l"(&g_bar), "r"(1u) : "memory");
        }
        __syncthreads();
    }

    // ---------------- FC worker role (3-term fp16, 64-d tiles) ----------------
    unsigned* itemp = (unsigned*)(smem + S_ITEM);
    for (;;) {
        __syncthreads();
        if (tid == 0) *itemp = atomicAdd(&g_fcitem, 1u);
        __syncthreads();
        unsigned item = *itemp;
        if (item >= 4096u) break;
        int s = (int)(item >> 4), dt = (int)(item & 15);

        if (tid == 0) {
            unsigned tgt = (unsigned)(NLSTM * (s + 1)), v;
            do {
                asm volatile("ld.acquire.gpu.global.u32 %0, [%1];" : "=r"(v) : "l"(&g_bar));
                if ((int)(v - tgt) >= 0) break;
                __nanosleep(64);
            } while (1);
        }
        __syncthreads();

        const unsigned char* aH = g_Ahi + (size_t)(s + 1) * SLOTP;
        const unsigned char* aL = g_Alo + (size_t)(s + 1) * SLOTP;
        const unsigned char* bH = g_FcHi + (size_t)dt * FCDP;
        const unsigned char* bL = g_FcLo + (size_t)dt * FCDP;

        auto issueF = [&](int kc) {
            uint32_t d = sb + (kc & 1) * FBUF;
            const unsigned char* s0 = aH + (size_t)kc * ACHP;
            const unsigned char* s1 = aL + (size_t)kc * ACHP;
            const unsigned char* s2 = bH + (size_t)kc * FCCH;
            const unsigned char* s3 = bL + (size_t)kc * FCCH;
            for (int i = tid; i < 1152; i += 256) cpa16(d + i * 16, s0 + i * 16);
            for (int i = tid; i < 1152; i += 256) cpa16(d + 18432 + i * 16, s1 + i * 16);
            for (int i = tid; i < 576; i += 256) cpa16(d + 36864 + i * 16, s2 + i * 16);
            for (int i = tid; i < 576; i += 256) cpa16(d + 46080 + i * 16, s3 + i * 16);
            CP_COMMIT();
        };

        float accH[8][4], accX[8][4];
#pragma unroll
        for (int n = 0; n < 8; n++)
#pragma unroll
            for (int q = 0; q < 4; q++) { accH[n][q] = 0.f; accX[n][q] = 0.f; }

        issueF(0); issueF(1);
        for (int kc = 0; kc < 16; kc++) {
            if (kc == 15) CP_WAIT0(); else CP_WAIT1();
            __syncthreads();
            const unsigned char* As = smem + (kc & 1) * FBUF;
            const unsigned char* Al = As + 18432;
            const unsigned char* Bh = As + 36864;
            const unsigned char* Bl = As + 46080;
            const int rb = (16 * w + g) * 144 + tig * 4;
#pragma unroll
            for (int ks = 0; ks < 4; ks++) {
                const int ao = rb + ks * 32;
                uint32_t ah[4], al4[4];
                ah[0] = *(const uint32_t*)(As + ao);
                ah[1] = *(const uint32_t*)(As + ao + 1152);
                ah[2] = *(const uint32_t*)(As + ao + 16);
                ah[3] = *(const uint32_t*)(As + ao + 1168);
                al4[0] = *(const uint32_t*)(Al + ao);
                al4[1] = *(const uint32_t*)(Al + ao + 1152);
                al4[2] = *(const uint32_t*)(Al + ao + 16);
                al4[3] = *(const uint32_t*)(Al + ao + 1168);
#pragma unroll
                for (int nt = 0; nt < 8; nt++) {
                    const int bo = (8 * nt + g) * 144 + tig * 4 + ks * 32;
                    uint32_t bh0 = *(const uint32_t*)(Bh + bo);
                    uint32_t bh1 = *(const uint32_t*)(Bh + bo + 16);
                    uint32_t bl0 = *(const uint32_t*)(Bl + bo);
                    uint32_t bl1 = *(const uint32_t*)(Bl + bo + 16);
                    hmma(accH[nt], ah, bh0, bh1);   // xh*wh
                    hmma(accX[nt], al4, bh0, bh1);  // xl*wh (scaled)
                    hmma(accX[nt], ah, bl0, bl1);   // xh*wl (scaled)
                }
            }
            __syncthreads();
            if (kc + 2 < 16) issueF(kc + 2);
        }

#pragma unroll
        for (int nt = 0; nt < 8; nt++) {
            int d = dt * 64 + 8 * nt + 2 * tig;
            float2 bb = *(const float2*)(bfc + d);
            int n0 = 16 * w + g;
            float2 v0 = make_float2(accH[nt][0] + accX[nt][0] * RINV + bb.x,
                                    accH[nt][1] + accX[nt][1] * RINV + bb.y);
            float2 v1 = make_float2(accH[nt][2] + accX[nt][2] * RINV + bb.x,
                                    accH[nt][3] + accX[nt][3] * RINV + bb.y);
            *(float2*)(out + ((size_t)n0 * TT + s) * 1024 + d) = v0;
            *(float2*)(out + ((size_t)(n0 + 8) * TT + s) * 1024 + d) = v1;
        }
    }
}

// ------------------------- launch -------------------------
extern "C" void kernel_launch(void* const* d_in, const int* in_sizes, int n_in,
                              void* d_out, int out_size)
{
    const float* hT  = (const float*)d_in[0];
    const float* Wih = (const float*)d_in[1];
    const float* Whh = (const float*)d_in[2];
    const float* bih = (const float*)d_in[3];
    const float* bhh = (const float*)d_in[4];
    const float* Wfc = (const float*)d_in[5];
    const float* bfc = (const float*)d_in[6];
    float* out = (float*)d_out;

    static int total = 0;
    if (total == 0) {
        int smc = 148;
        if (cudaDeviceGetAttribute(&smc, cudaDevAttrMultiProcessorCount, 0) != cudaSuccess)
            smc = 148;
        total = smc < 129 ? 129 : (smc > 192 ? 192 : smc);
        cudaFuncSetAttribute(lstm_fused, cudaFuncAttributeMaxDynamicSharedMemorySize, SM_ALL);
    }

    prep<<<1024, 256>>>(hT, Wih, Whh, bih, bhh, Wfc);
    lstm_fused<<<total, 256, SM_ALL>>>(bfc, out);
}